// round 1
// baseline (speedup 1.0000x reference)
#include <cuda_runtime.h>
#include <cuda_bf16.h>

// ---------------- problem constants ----------------
#define NTOK   2048          // B*T
#define DMODEL 768
#define DQF    1024          // PKM query width (PH*DHK*2)
#define NHEAD  12
#define DHEAD  64
#define NK     256
#define TOPK   32

// ---------------- scratch (device globals; no allocation allowed) ----------------
__device__ float g_h   [NTOK * DMODEL];      // LN output (reused for LN1 and LN2)
__device__ float g_q   [NTOK * DMODEL];
__device__ float g_k   [NTOK * DMODEL];
__device__ float g_v   [NTOK * DMODEL];
__device__ float g_att [NTOK * DMODEL];      // attention output pre-projection
__device__ float g_qf  [NTOK * DQF];         // PKM query pre-BN
__device__ float g_qn  [NTOK * DQF];         // PKM query post-BN
__device__ float g_mu  [DQF];
__device__ float g_rstd[DQF];
__device__ float g_bns [16 * DQF];           // BN partial sums
__device__ float g_bns2[16 * DQF];
__device__ float g_keysT[8 * 128 * 256];     // keys transposed: [z=4p+h][d][k]
__device__ float g_dots [NTOK * 8 * 256];    // [n][z=4p+h][k]
__device__ float g_w    [NTOK * 4 * TOPK];   // final softmax weights
__device__ int   g_vi   [NTOK * 4 * TOPK];   // value-row indices

// ---------------- LayerNorm: one block per row ----------------
__global__ void ln_kernel(const float* __restrict__ X,
                          const float* __restrict__ gamma,
                          const float* __restrict__ beta)
{
    int n = blockIdx.x;
    int tid = threadIdx.x;                    // 256 threads
    const float* x = X + (size_t)n * DMODEL;
    float v[3];
    float s = 0.f, s2 = 0.f;
    #pragma unroll
    for (int i = 0; i < 3; i++) {
        v[i] = x[tid + i * 256];
        s += v[i]; s2 += v[i] * v[i];
    }
    #pragma unroll
    for (int o = 16; o > 0; o >>= 1) {
        s  += __shfl_xor_sync(0xffffffffu, s,  o);
        s2 += __shfl_xor_sync(0xffffffffu, s2, o);
    }
    __shared__ float rs[8], rs2[8];
    int w = tid >> 5;
    if ((tid & 31) == 0) { rs[w] = s; rs2[w] = s2; }
    __syncthreads();
    if (tid < 32) {
        s  = (tid < 8) ? rs[tid]  : 0.f;
        s2 = (tid < 8) ? rs2[tid] : 0.f;
        #pragma unroll
        for (int o = 4; o > 0; o >>= 1) {
            s  += __shfl_xor_sync(0xffffffffu, s,  o);
            s2 += __shfl_xor_sync(0xffffffffu, s2, o);
        }
        if (tid == 0) { rs[0] = s; rs2[0] = s2; }
    }
    __syncthreads();
    float mean = rs[0] * (1.f / DMODEL);
    float var  = rs2[0] * (1.f / DMODEL) - mean * mean;
    float rstd = rsqrtf(var + 1e-5f);
    #pragma unroll
    for (int i = 0; i < 3; i++) {
        int c = tid + i * 256;
        g_h[(size_t)n * DMODEL + c] = (v[i] - mean) * rstd * gamma[c] + beta[c];
    }
}

// ---------------- SGEMM: C = A @ W (+bias) (+resid); 128x128x8 tile, 8x8/thread ----
__global__ __launch_bounds__(256)
void sgemm_kernel(const float* __restrict__ A, int lda, int aZ,
                  const float* __restrict__ W, int ldw, int wZ,
                  const float* __restrict__ bias,
                  const float* __restrict__ resid, int ldr,
                  float* __restrict__ C, int ldc, int cZ, int Kin)
{
    int z = blockIdx.z;
    A += (size_t)z * aZ; W += (size_t)z * wZ; C += (size_t)z * cZ;
    __shared__ float As[8][128];
    __shared__ float Bs[8][128];
    int tid = threadIdx.x;
    int tx = tid & 15, ty = tid >> 4;
    int rowBase = blockIdx.y * 128, colBase = blockIdx.x * 128;
    float acc[8][8];
    #pragma unroll
    for (int i = 0; i < 8; i++)
        #pragma unroll
        for (int j = 0; j < 8; j++) acc[i][j] = 0.f;

    int aRow = tid >> 1, aCol = (tid & 1) * 4;
    int bRow = tid >> 5, bCol = (tid & 31) * 4;
    const float* Ap = A + (size_t)(rowBase + aRow) * lda + aCol;
    const float* Wp = W + (size_t)bRow * ldw + colBase + bCol;

    for (int k0 = 0; k0 < Kin; k0 += 8) {
        float4 av = *(const float4*)(Ap + k0);
        float4 bv = *(const float4*)(Wp + (size_t)k0 * ldw);
        As[aCol + 0][aRow] = av.x; As[aCol + 1][aRow] = av.y;
        As[aCol + 2][aRow] = av.z; As[aCol + 3][aRow] = av.w;
        *(float4*)&Bs[bRow][bCol] = bv;
        __syncthreads();
        #pragma unroll
        for (int kk = 0; kk < 8; kk++) {
            float a[8], b[8];
            *(float4*)&a[0] = *(const float4*)&As[kk][ty * 8];
            *(float4*)&a[4] = *(const float4*)&As[kk][ty * 8 + 4];
            *(float4*)&b[0] = *(const float4*)&Bs[kk][tx * 8];
            *(float4*)&b[4] = *(const float4*)&Bs[kk][tx * 8 + 4];
            #pragma unroll
            for (int i = 0; i < 8; i++)
                #pragma unroll
                for (int j = 0; j < 8; j++) acc[i][j] += a[i] * b[j];
        }
        __syncthreads();
    }
    int row = rowBase + ty * 8, col = colBase + tx * 8;
    #pragma unroll
    for (int i = 0; i < 8; i++) {
        float out[8];
        #pragma unroll
        for (int j = 0; j < 8; j++) {
            float vv = acc[i][j];
            if (bias)  vv += bias[col + j];
            if (resid) vv += resid[(size_t)(row + i) * ldr + col + j];
            out[j] = vv;
        }
        *(float4*)&C[(size_t)(row + i) * ldc + col]     = *(float4*)&out[0];
        *(float4*)&C[(size_t)(row + i) * ldc + col + 4] = *(float4*)&out[4];
    }
}

// ---------------- attention: flash-style; block = 128 queries of one (b,h) ------
__global__ __launch_bounds__(128)
void attn_kernel(const float* __restrict__ Q, const float* __restrict__ K,
                 const float* __restrict__ V, float* __restrict__ O)
{
    __shared__ float Ks[64][64];
    __shared__ float Vs[64][64];
    int bh = blockIdx.x;
    int b = bh / NHEAD, h = bh % NHEAD;
    int tid = threadIdx.x;
    int t = blockIdx.y * 128 + tid;
    size_t qoff = (size_t)(b * 1024 + t) * DMODEL + h * DHEAD;

    float q[64], o[64];
    #pragma unroll
    for (int i = 0; i < 16; i++) {
        float4 f = *(const float4*)&Q[qoff + i * 4];
        q[i*4] = f.x; q[i*4+1] = f.y; q[i*4+2] = f.z; q[i*4+3] = f.w;
    }
    #pragma unroll
    for (int d = 0; d < 64; d++) o[d] = 0.f;
    float m = -1e30f, l = 0.f;

    size_t kbase = (size_t)(b * 1024) * DMODEL + h * DHEAD;
    for (int kt = 0; kt < 16; kt++) {
        for (int i = tid; i < 64 * 16; i += 128) {
            int j = i >> 4, c = (i & 15) << 2;
            size_t off = kbase + (size_t)(kt * 64 + j) * DMODEL + c;
            *(float4*)&Ks[j][c] = *(const float4*)&K[off];
            *(float4*)&Vs[j][c] = *(const float4*)&V[off];
        }
        __syncthreads();
        for (int j = 0; j < 64; j++) {
            float s = 0.f;
            #pragma unroll
            for (int c = 0; c < 16; c++) {
                float4 kv = *(const float4*)&Ks[j][c * 4];
                s += q[c*4] * kv.x + q[c*4+1] * kv.y + q[c*4+2] * kv.z + q[c*4+3] * kv.w;
            }
            s *= 0.125f;                         // 1/sqrt(64)
            if (s > m) {                          // rare: amortized O(log) rescales
                float corr = __expf(m - s);
                l *= corr;
                #pragma unroll
                for (int d = 0; d < 64; d++) o[d] *= corr;
                m = s;
            }
            float p = __expf(s - m);
            l += p;
            #pragma unroll
            for (int c = 0; c < 16; c++) {
                float4 vv = *(const float4*)&Vs[j][c * 4];
                o[c*4]   += p * vv.x; o[c*4+1] += p * vv.y;
                o[c*4+2] += p * vv.z; o[c*4+3] += p * vv.w;
            }
        }
        __syncthreads();
    }
    float inv = 1.f / l;
    #pragma unroll
    for (int i = 0; i < 16; i++) {
        float4 f;
        f.x = o[i*4] * inv; f.y = o[i*4+1] * inv;
        f.z = o[i*4+2] * inv; f.w = o[i*4+3] * inv;
        *(float4*)&O[qoff + i * 4] = f;
    }
}

// ---------------- BatchNorm over tokens (training-mode batch stats) -------------
__global__ void bn_partial_kernel()
{
    int c  = blockIdx.x * 256 + threadIdx.x;  // column, gridDim.x = 4
    int r0 = blockIdx.y * 128;                // row chunk, gridDim.y = 16
    float s = 0.f, s2 = 0.f;
    #pragma unroll 4
    for (int n = 0; n < 128; n++) {
        float v = g_qf[(size_t)(r0 + n) * DQF + c];
        s += v; s2 += v * v;
    }
    g_bns [blockIdx.y * DQF + c] = s;
    g_bns2[blockIdx.y * DQF + c] = s2;
}

__global__ void bn_finish_kernel()
{
    int c = blockIdx.x * 256 + threadIdx.x;
    float s = 0.f, s2 = 0.f;
    #pragma unroll
    for (int i = 0; i < 16; i++) { s += g_bns[i * DQF + c]; s2 += g_bns2[i * DQF + c]; }
    float mu  = s * (1.f / NTOK);
    float var = s2 * (1.f / NTOK) - mu * mu;
    g_mu[c]   = mu;
    g_rstd[c] = rsqrtf(var + 1e-5f);
}

__global__ void bn_apply_kernel(const float* __restrict__ gam, const float* __restrict__ bet)
{
    int n = blockIdx.x;
    int c = threadIdx.x * 4;
    float4 v  = *(const float4*)&g_qf[(size_t)n * DQF + c];
    float4 mu = *(const float4*)&g_mu[c];
    float4 rs = *(const float4*)&g_rstd[c];
    float4 gg = *(const float4*)&gam[c];
    float4 bb = *(const float4*)&bet[c];
    float4 r;
    r.x = (v.x - mu.x) * rs.x * gg.x + bb.x;
    r.y = (v.y - mu.y) * rs.y * gg.y + bb.y;
    r.z = (v.z - mu.z) * rs.z * gg.z + bb.z;
    r.w = (v.w - mu.w) * rs.w * gg.w + bb.w;
    *(float4*)&g_qn[(size_t)n * DQF + c] = r;
}

// ---------------- transpose PKM keys into [z=4p+h][d][k] ------------------------
__global__ void keysT_kernel(const float* __restrict__ keys)
{
    int idx = blockIdx.x * 256 + threadIdx.x;   // 0 .. 262143
    int k  = idx & 255;
    int d  = (idx >> 8) & 127;
    int zz = idx >> 15;                          // z = 4p + h
    int h = zz & 3, p = zz >> 2;
    // keys layout: [PH=4][NK=256][2][DHK=128]
    g_keysT[idx] = keys[(((size_t)(h * 256 + k)) * 2 + p) * 128 + d];
}

// ---------------- PKM top-k: per (n,h) block; bitonic sorts ---------------------
__global__ __launch_bounds__(256)
void topk_kernel()
{
    __shared__ float sv[512];
    __shared__ int   si[512];
    __shared__ float cv[1024];
    __shared__ int   ci[1024];
    int h = blockIdx.x, n = blockIdx.y;
    int tid = threadIdx.x;
    const float* d0 = g_dots + (size_t)n * 2048 + h * 256;        // z = h   (p=0)
    const float* d1 = g_dots + (size_t)n * 2048 + (4 + h) * 256;  // z = 4+h (p=1)
    sv[tid]       = d0[tid]; si[tid]       = tid;
    sv[256 + tid] = d1[tid]; si[256 + tid] = tid;
    __syncthreads();

    // sort both 256-element halves descending (threads 0-127 half0, 128-255 half1)
    {
        int half = tid >> 7;
        int t    = tid & 127;
        int base = half << 8;
        for (int k = 2; k <= 256; k <<= 1) {
            for (int j = k >> 1; j > 0; j >>= 1) {
                int i = ((t & ~(j - 1)) << 1) | (t & (j - 1));
                int l = i | j;
                float va = sv[base + i], vb = sv[base + l];
                int   ia = si[base + i], ib = si[base + l];
                bool gt  = (va > vb) || (va == vb && ia < ib);
                bool dir = ((i & k) == 0);
                if (dir != gt) {
                    sv[base + i] = vb; sv[base + l] = va;
                    si[base + i] = ib; si[base + l] = ia;
                }
                __syncthreads();
            }
        }
    }
    // cartesian sums of top32 x top32
    for (int e = tid; e < 1024; e += 256) {
        int i = e >> 5, j = e & 31;
        cv[e] = sv[i] + sv[256 + j];
        ci[e] = si[i] * NK + si[256 + j];
    }
    __syncthreads();
    // sort 1024 descending; 512 pairs/substage, 2 per thread
    for (int k = 2; k <= 1024; k <<= 1) {
        for (int j = k >> 1; j > 0; j >>= 1) {
            #pragma unroll
            for (int p = 0; p < 2; p++) {
                int t = tid + (p << 8);
                int i = ((t & ~(j - 1)) << 1) | (t & (j - 1));
                int l = i | j;
                float va = cv[i], vb = cv[l];
                int   ia = ci[i], ib = ci[l];
                bool gt  = (va > vb) || (va == vb && ia < ib);
                bool dir = ((i & k) == 0);
                if (dir != gt) {
                    cv[i] = vb; cv[l] = va;
                    ci[i] = ib; ci[l] = ia;
                }
            }
            __syncthreads();
        }
    }
    // softmax over top-32 and emit
    if (tid < 32) {
        float mx = cv[0];
        float e = __expf(cv[tid] - mx);
        float s = e;
        #pragma unroll
        for (int o = 16; o > 0; o >>= 1) s += __shfl_xor_sync(0xffffffffu, s, o);
        size_t off = ((size_t)n * 4 + h) * TOPK + tid;
        g_w [off] = e / s;
        g_vi[off] = ci[tid];
    }
}

// ---------------- EmbeddingBag gather + residual add ----------------------------
__global__ __launch_bounds__(256)
void gather_kernel(const float* __restrict__ values, float* __restrict__ out)
{
    int n = blockIdx.x;
    int tid = threadIdx.x;
    __shared__ float ws[128];
    __shared__ int   is[128];
    if (tid < 128) {
        ws[tid] = g_w [(size_t)n * 128 + tid];
        is[tid] = g_vi[(size_t)n * 128 + tid];
    }
    __syncthreads();
    float a0 = 0.f, a1 = 0.f, a2 = 0.f;
    #pragma unroll 4
    for (int m = 0; m < 128; m++) {
        const float* vp = values + (size_t)is[m] * DMODEL;
        float wm = ws[m];
        a0 += wm * vp[tid];
        a1 += wm * vp[tid + 256];
        a2 += wm * vp[tid + 512];
    }
    size_t o = (size_t)n * DMODEL + tid;
    out[o]       += a0;
    out[o + 256] += a1;
    out[o + 512] += a2;
}

// ---------------- launch ---------------------------------------------------------
extern "C" void kernel_launch(void* const* d_in, const int* in_sizes, int n_in,
                              void* d_out, int out_size)
{
    const float* x     = (const float*)d_in[0];
    const float* wq    = (const float*)d_in[1];
    const float* bq    = (const float*)d_in[2];
    const float* wk    = (const float*)d_in[3];
    const float* bk    = (const float*)d_in[4];
    const float* wv    = (const float*)d_in[5];
    const float* bv    = (const float*)d_in[6];
    const float* wo    = (const float*)d_in[7];
    const float* bo    = (const float*)d_in[8];
    const float* ln1g  = (const float*)d_in[9];
    const float* ln1b  = (const float*)d_in[10];
    const float* ln2g  = (const float*)d_in[11];
    const float* ln2b  = (const float*)d_in[12];
    const float* pkmwq = (const float*)d_in[13];
    const float* bng   = (const float*)d_in[14];
    const float* bnb   = (const float*)d_in[15];
    const float* keys  = (const float*)d_in[16];
    const float* vals  = (const float*)d_in[17];
    float* out = (float*)d_out;

    float *ph, *pq, *pk, *pv, *patt, *pqf, *pqn, *pkeysT, *pdots;
    cudaGetSymbolAddress((void**)&ph,     g_h);
    cudaGetSymbolAddress((void**)&pq,     g_q);
    cudaGetSymbolAddress((void**)&pk,     g_k);
    cudaGetSymbolAddress((void**)&pv,     g_v);
    cudaGetSymbolAddress((void**)&patt,   g_att);
    cudaGetSymbolAddress((void**)&pqf,    g_qf);
    cudaGetSymbolAddress((void**)&pqn,    g_qn);
    cudaGetSymbolAddress((void**)&pkeysT, g_keysT);
    cudaGetSymbolAddress((void**)&pdots,  g_dots);

    // ---- attention block ----
    ln_kernel<<<NTOK, 256>>>(x, ln1g, ln1b);
    dim3 gProj(DMODEL / 128, NTOK / 128, 1);
    sgemm_kernel<<<gProj, 256>>>(ph, DMODEL, 0, wq, DMODEL, 0, bq, nullptr, 0, pq, DMODEL, 0, DMODEL);
    sgemm_kernel<<<gProj, 256>>>(ph, DMODEL, 0, wk, DMODEL, 0, bk, nullptr, 0, pk, DMODEL, 0, DMODEL);
    sgemm_kernel<<<gProj, 256>>>(ph, DMODEL, 0, wv, DMODEL, 0, bv, nullptr, 0, pv, DMODEL, 0, DMODEL);
    attn_kernel<<<dim3(2 * NHEAD, 8), 128>>>(pq, pk, pv, patt);
    // x1 = x + attn @ wo + bo  -> d_out
    sgemm_kernel<<<gProj, 256>>>(patt, DMODEL, 0, wo, DMODEL, 0, bo, x, DMODEL, out, DMODEL, 0, DMODEL);

    // ---- PKM block ----
    ln_kernel<<<NTOK, 256>>>(out, ln2g, ln2b);
    sgemm_kernel<<<dim3(DQF / 128, NTOK / 128, 1), 256>>>(ph, DMODEL, 0, pkmwq, DQF, 0,
                                                          nullptr, nullptr, 0, pqf, DQF, 0, DMODEL);
    bn_partial_kernel<<<dim3(4, 16), 256>>>();
    bn_finish_kernel<<<4, 256>>>();
    bn_apply_kernel<<<NTOK, 256>>>(bng, bnb);
    keysT_kernel<<<1024, 256>>>(keys);
    // dots: 8 batched GEMMs (z = 4p+h), A offset = 128*z, C col offset = 256*z
    sgemm_kernel<<<dim3(2, 16, 8), 256>>>(pqn, DQF, 128, pkeysT, 256, 128 * 256,
                                          nullptr, nullptr, 0, pdots, 2048, 256, 128);
    topk_kernel<<<dim3(4, NTOK), 256>>>();
    gather_kernel<<<NTOK, 256>>>(vals, out);
}

// round 3
// speedup vs baseline: 1.2810x; 1.2810x over previous
#include <cuda_runtime.h>
#include <cuda_bf16.h>

// ---------------- problem constants ----------------
#define NTOK   2048          // B*T
#define DMODEL 768
#define DQF    1024          // PKM query width (PH*DHK*2)
#define NHEAD  12
#define DHEAD  64
#define NK     256
#define TOPK   32

// ---------------- scratch (device globals; no allocation allowed) ----------------
__device__ float g_h   [NTOK * DMODEL];      // LN output (reused for LN1 and LN2)
__device__ float g_q   [NTOK * DMODEL];
__device__ float g_k   [NTOK * DMODEL];
__device__ float g_v   [NTOK * DMODEL];
__device__ float g_att [NTOK * DMODEL];      // attention output pre-projection
__device__ float g_qf  [NTOK * DQF];         // PKM query pre-BN
__device__ float g_qn  [NTOK * DQF];         // PKM query post-BN
__device__ float g_mu  [DQF];
__device__ float g_rstd[DQF];
__device__ float g_bns [16 * DQF];           // BN partial sums
__device__ float g_bns2[16 * DQF];
__device__ float g_keysT[8 * 128 * 256];     // keys transposed: [z=4p+h][d][k]
__device__ float g_dots [NTOK * 8 * 256];    // [n][z=4p+h][k]
__device__ float g_w    [NTOK * 4 * TOPK];   // final softmax weights
__device__ int   g_vi   [NTOK * 4 * TOPK];   // value-row indices

// ---------------- LayerNorm: one block per row ----------------
__global__ void ln_kernel(const float* __restrict__ X,
                          const float* __restrict__ gamma,
                          const float* __restrict__ beta)
{
    int n = blockIdx.x;
    int tid = threadIdx.x;                    // 256 threads
    const float* x = X + (size_t)n * DMODEL;
    float v[3];
    float s = 0.f, s2 = 0.f;
    #pragma unroll
    for (int i = 0; i < 3; i++) {
        v[i] = x[tid + i * 256];
        s += v[i]; s2 += v[i] * v[i];
    }
    #pragma unroll
    for (int o = 16; o > 0; o >>= 1) {
        s  += __shfl_xor_sync(0xffffffffu, s,  o);
        s2 += __shfl_xor_sync(0xffffffffu, s2, o);
    }
    __shared__ float rs[8], rs2[8];
    int w = tid >> 5;
    if ((tid & 31) == 0) { rs[w] = s; rs2[w] = s2; }
    __syncthreads();
    if (tid < 32) {
        s  = (tid < 8) ? rs[tid]  : 0.f;
        s2 = (tid < 8) ? rs2[tid] : 0.f;
        #pragma unroll
        for (int o = 4; o > 0; o >>= 1) {
            s  += __shfl_xor_sync(0xffffffffu, s,  o);
            s2 += __shfl_xor_sync(0xffffffffu, s2, o);
        }
        if (tid == 0) { rs[0] = s; rs2[0] = s2; }
    }
    __syncthreads();
    float mean = rs[0] * (1.f / DMODEL);
    float var  = rs2[0] * (1.f / DMODEL) - mean * mean;
    float rstd = rsqrtf(var + 1e-5f);
    #pragma unroll
    for (int i = 0; i < 3; i++) {
        int c = tid + i * 256;
        g_h[(size_t)n * DMODEL + c] = (v[i] - mean) * rstd * gamma[c] + beta[c];
    }
}

// ---------------- batched SGEMM: C[z] = (A+aOff[z]) @ W[z] (+bias[z]) (+resid) ----
// tile 128x64, 256 threads, 8x4 per thread, double-buffered smem, Ktile=16
struct GemmArgs {
    const float* A;
    const float* W[8];
    const float* bias[8];
    const float* resid;
    float*       C[8];
    int lda, ldw, ldr, ldc, K;
    int aOff[8];
};

__global__ __launch_bounds__(256)
void gemm_kernel(GemmArgs g)
{
    __shared__ float As[2][16][128];
    __shared__ float Bs[2][16][64];
    int z = blockIdx.z;
    const float* A    = g.A + g.aOff[z];
    const float* W    = g.W[z];
    const float* bias = g.bias[z];
    float*       C    = g.C[z];
    int tid = threadIdx.x;
    int tx = tid & 15, ty = tid >> 4;
    int rowBase = blockIdx.y * 128, colBase = blockIdx.x * 64;

    // A-tile load map: 128 rows x 16 k; thread -> row=tid>>1, 8 contiguous k
    int aRow = tid >> 1, aC8 = (tid & 1) * 8;
    // B-tile load map: 16 k-rows x 64 cols; thread -> row=tid>>4, float4 col
    int bRow = tid >> 4, bC4 = (tid & 15) * 4;
    const float* Ap = A + (size_t)(rowBase + aRow) * g.lda + aC8;
    const float* Wp = W + (size_t)bRow * g.ldw + colBase + bC4;

    float acc[8][4];
    #pragma unroll
    for (int i = 0; i < 8; i++)
        #pragma unroll
        for (int j = 0; j < 4; j++) acc[i][j] = 0.f;

    int KT = g.K >> 4;
    float4 pa0 = *(const float4*)(Ap);
    float4 pa1 = *(const float4*)(Ap + 4);
    float4 pb  = *(const float4*)(Wp);
    As[0][aC8 + 0][aRow] = pa0.x; As[0][aC8 + 1][aRow] = pa0.y;
    As[0][aC8 + 2][aRow] = pa0.z; As[0][aC8 + 3][aRow] = pa0.w;
    As[0][aC8 + 4][aRow] = pa1.x; As[0][aC8 + 5][aRow] = pa1.y;
    As[0][aC8 + 6][aRow] = pa1.z; As[0][aC8 + 7][aRow] = pa1.w;
    *(float4*)&Bs[0][bRow][bC4] = pb;
    __syncthreads();

    for (int kt = 0; kt < KT; kt++) {
        int cur = kt & 1;
        if (kt + 1 < KT) {
            int k0 = (kt + 1) << 4;
            pa0 = *(const float4*)(Ap + k0);
            pa1 = *(const float4*)(Ap + k0 + 4);
            pb  = *(const float4*)(Wp + (size_t)k0 * g.ldw);
        }
        #pragma unroll
        for (int kk = 0; kk < 16; kk++) {
            float a[8], b[4];
            *(float4*)&a[0] = *(const float4*)&As[cur][kk][ty * 8];
            *(float4*)&a[4] = *(const float4*)&As[cur][kk][ty * 8 + 4];
            *(float4*)&b[0] = *(const float4*)&Bs[cur][kk][tx * 4];
            #pragma unroll
            for (int i = 0; i < 8; i++)
                #pragma unroll
                for (int j = 0; j < 4; j++) acc[i][j] += a[i] * b[j];
        }
        if (kt + 1 < KT) {
            int nxt = (kt + 1) & 1;
            As[nxt][aC8 + 0][aRow] = pa0.x; As[nxt][aC8 + 1][aRow] = pa0.y;
            As[nxt][aC8 + 2][aRow] = pa0.z; As[nxt][aC8 + 3][aRow] = pa0.w;
            As[nxt][aC8 + 4][aRow] = pa1.x; As[nxt][aC8 + 5][aRow] = pa1.y;
            As[nxt][aC8 + 6][aRow] = pa1.z; As[nxt][aC8 + 7][aRow] = pa1.w;
            *(float4*)&Bs[nxt][bRow][bC4] = pb;
        }
        __syncthreads();
    }

    int row = rowBase + ty * 8, col = colBase + tx * 4;
    #pragma unroll
    for (int i = 0; i < 8; i++) {
        float out[4];
        #pragma unroll
        for (int j = 0; j < 4; j++) {
            float vv = acc[i][j];
            if (bias)    vv += bias[col + j];
            if (g.resid) vv += g.resid[(size_t)(row + i) * g.ldr + col + j];
            out[j] = vv;
        }
        *(float4*)&C[(size_t)(row + i) * g.ldc + col] = *(float4*)&out[0];
    }
}

// ---------------- attention: flash-style; block = 128 queries of one (b,h) ------
__global__ __launch_bounds__(128)
void attn_kernel(const float* __restrict__ Q, const float* __restrict__ K,
                 const float* __restrict__ V, float* __restrict__ O)
{
    __shared__ float Ks[64][64];
    __shared__ float Vs[64][64];
    int bh = blockIdx.x;
    int b = bh / NHEAD, h = bh % NHEAD;
    int tid = threadIdx.x;
    int t = blockIdx.y * 128 + tid;
    size_t qoff = (size_t)(b * 1024 + t) * DMODEL + h * DHEAD;

    float q[64], o[64];
    #pragma unroll
    for (int i = 0; i < 16; i++) {
        float4 f = *(const float4*)&Q[qoff + i * 4];
        q[i*4] = f.x; q[i*4+1] = f.y; q[i*4+2] = f.z; q[i*4+3] = f.w;
    }
    #pragma unroll
    for (int d = 0; d < 64; d++) o[d] = 0.f;
    float m = -1e30f, l = 0.f;

    size_t kbase = (size_t)(b * 1024) * DMODEL + h * DHEAD;
    for (int kt = 0; kt < 16; kt++) {
        for (int i = tid; i < 64 * 16; i += 128) {
            int j = i >> 4, c = (i & 15) << 2;
            size_t off = kbase + (size_t)(kt * 64 + j) * DMODEL + c;
            *(float4*)&Ks[j][c] = *(const float4*)&K[off];
            *(float4*)&Vs[j][c] = *(const float4*)&V[off];
        }
        __syncthreads();
        for (int j = 0; j < 64; j++) {
            float s = 0.f;
            #pragma unroll
            for (int c = 0; c < 16; c++) {
                float4 kv = *(const float4*)&Ks[j][c * 4];
                s += q[c*4] * kv.x + q[c*4+1] * kv.y + q[c*4+2] * kv.z + q[c*4+3] * kv.w;
            }
            s *= 0.125f;                         // 1/sqrt(64)
            if (s > m) {                          // rare: amortized rescale
                float corr = __expf(m - s);
                l *= corr;
                #pragma unroll
                for (int d = 0; d < 64; d++) o[d] *= corr;
                m = s;
            }
            float p = __expf(s - m);
            l += p;
            #pragma unroll
            for (int c = 0; c < 16; c++) {
                float4 vv = *(const float4*)&Vs[j][c * 4];
                o[c*4]   += p * vv.x; o[c*4+1] += p * vv.y;
                o[c*4+2] += p * vv.z; o[c*4+3] += p * vv.w;
            }
        }
        __syncthreads();
    }
    float inv = 1.f / l;
    #pragma unroll
    for (int i = 0; i < 16; i++) {
        float4 f;
        f.x = o[i*4] * inv; f.y = o[i*4+1] * inv;
        f.z = o[i*4+2] * inv; f.w = o[i*4+3] * inv;
        *(float4*)&O[qoff + i * 4] = f;
    }
}

// ---------------- BatchNorm over tokens (training-mode batch stats) -------------
__global__ void bn_partial_kernel()
{
    int c  = blockIdx.x * 256 + threadIdx.x;  // column, gridDim.x = 4
    int r0 = blockIdx.y * 128;                // row chunk, gridDim.y = 16
    float s = 0.f, s2 = 0.f;
    #pragma unroll 4
    for (int n = 0; n < 128; n++) {
        float v = g_qf[(size_t)(r0 + n) * DQF + c];
        s += v; s2 += v * v;
    }
    g_bns [blockIdx.y * DQF + c] = s;
    g_bns2[blockIdx.y * DQF + c] = s2;
}

__global__ void bn_finish_kernel()
{
    int c = blockIdx.x * 256 + threadIdx.x;
    float s = 0.f, s2 = 0.f;
    #pragma unroll
    for (int i = 0; i < 16; i++) { s += g_bns[i * DQF + c]; s2 += g_bns2[i * DQF + c]; }
    float mu  = s * (1.f / NTOK);
    float var = s2 * (1.f / NTOK) - mu * mu;
    g_mu[c]   = mu;
    g_rstd[c] = rsqrtf(var + 1e-5f);
}

__global__ void bn_apply_kernel(const float* __restrict__ gam, const float* __restrict__ bet)
{
    int n = blockIdx.x;
    int c = threadIdx.x * 4;
    float4 v  = *(const float4*)&g_qf[(size_t)n * DQF + c];
    float4 mu = *(const float4*)&g_mu[c];
    float4 rs = *(const float4*)&g_rstd[c];
    float4 gg = *(const float4*)&gam[c];
    float4 bb = *(const float4*)&bet[c];
    float4 r;
    r.x = (v.x - mu.x) * rs.x * gg.x + bb.x;
    r.y = (v.y - mu.y) * rs.y * gg.y + bb.y;
    r.z = (v.z - mu.z) * rs.z * gg.z + bb.z;
    r.w = (v.w - mu.w) * rs.w * gg.w + bb.w;
    *(float4*)&g_qn[(size_t)n * DQF + c] = r;
}

// ---------------- transpose PKM keys into [z=4p+h][d][k] ------------------------
__global__ void keysT_kernel(const float* __restrict__ keys)
{
    int idx = blockIdx.x * 256 + threadIdx.x;   // 0 .. 262143
    int k  = idx & 255;
    int d  = (idx >> 8) & 127;
    int zz = idx >> 15;                          // z = 4p + h
    int h = zz & 3, p = zz >> 2;
    // keys layout: [PH=4][NK=256][2][DHK=128]
    g_keysT[idx] = keys[(((size_t)(h * 256 + k)) * 2 + p) * 128 + d];
}

// ---------------- PKM top-k: per (n,h) block; bitonic sorts ---------------------
__global__ __launch_bounds__(256)
void topk_kernel()
{
    __shared__ float sv[512];
    __shared__ int   si[512];
    __shared__ float cv[1024];
    __shared__ int   ci[1024];
    int h = blockIdx.x, n = blockIdx.y;
    int tid = threadIdx.x;
    const float* d0 = g_dots + (size_t)n * 2048 + h * 256;        // z = h   (p=0)
    const float* d1 = g_dots + (size_t)n * 2048 + (4 + h) * 256;  // z = 4+h (p=1)
    sv[tid]       = d0[tid]; si[tid]       = tid;
    sv[256 + tid] = d1[tid]; si[256 + tid] = tid;
    __syncthreads();

    // sort both 256-element halves descending (threads 0-127 half0, 128-255 half1)
    {
        int half = tid >> 7;
        int t    = tid & 127;
        int base = half << 8;
        for (int k = 2; k <= 256; k <<= 1) {
            for (int j = k >> 1; j > 0; j >>= 1) {
                int i = ((t & ~(j - 1)) << 1) | (t & (j - 1));
                int l = i | j;
                float va = sv[base + i], vb = sv[base + l];
                int   ia = si[base + i], ib = si[base + l];
                bool gt  = (va > vb) || (va == vb && ia < ib);
                bool dir = ((i & k) == 0);
                if (dir != gt) {
                    sv[base + i] = vb; sv[base + l] = va;
                    si[base + i] = ib; si[base + l] = ia;
                }
                __syncthreads();
            }
        }
    }
    // cartesian sums of top32 x top32
    for (int e = tid; e < 1024; e += 256) {
        int i = e >> 5, j = e & 31;
        cv[e] = sv[i] + sv[256 + j];
        ci[e] = si[i] * NK + si[256 + j];
    }
    __syncthreads();
    // sort 1024 descending; 512 pairs/substage, 2 per thread
    for (int k = 2; k <= 1024; k <<= 1) {
        for (int j = k >> 1; j > 0; j >>= 1) {
            #pragma unroll
            for (int p = 0; p < 2; p++) {
                int t = tid + (p << 8);
                int i = ((t & ~(j - 1)) << 1) | (t & (j - 1));
                int l = i | j;
                float va = cv[i], vb = cv[l];
                int   ia = ci[i], ib = ci[l];
                bool gt  = (va > vb) || (va == vb && ia < ib);
                bool dir = ((i & k) == 0);
                if (dir != gt) {
                    cv[i] = vb; cv[l] = va;
                    ci[i] = ib; ci[l] = ia;
                }
            }
            __syncthreads();
        }
    }
    // softmax over top-32 and emit
    if (tid < 32) {
        float mx = cv[0];
        float e = __expf(cv[tid] - mx);
        float s = e;
        #pragma unroll
        for (int o = 16; o > 0; o >>= 1) s += __shfl_xor_sync(0xffffffffu, s, o);
        size_t off = ((size_t)n * 4 + h) * TOPK + tid;
        g_w [off] = e / s;
        g_vi[off] = ci[tid];
    }
}

// ---------------- EmbeddingBag gather + residual add ----------------------------
__global__ __launch_bounds__(256)
void gather_kernel(const float* __restrict__ values, float* __restrict__ out)
{
    int n = blockIdx.x;
    int tid = threadIdx.x;
    __shared__ float ws[128];
    __shared__ int   is[128];
    if (tid < 128) {
        ws[tid] = g_w [(size_t)n * 128 + tid];
        is[tid] = g_vi[(size_t)n * 128 + tid];
    }
    __syncthreads();
    float a0 = 0.f, a1 = 0.f, a2 = 0.f;
    #pragma unroll 4
    for (int m = 0; m < 128; m++) {
        const float* vp = values + (size_t)is[m] * DMODEL;
        float wm = ws[m];
        a0 += wm * vp[tid];
        a1 += wm * vp[tid + 256];
        a2 += wm * vp[tid + 512];
    }
    size_t o = (size_t)n * DMODEL + tid;
    out[o]       += a0;
    out[o + 256] += a1;
    out[o + 512] += a2;
}

// ---------------- launch ---------------------------------------------------------
extern "C" void kernel_launch(void* const* d_in, const int* in_sizes, int n_in,
                              void* d_out, int out_size)
{
    const float* x     = (const float*)d_in[0];
    const float* wq    = (const float*)d_in[1];
    const float* bq    = (const float*)d_in[2];
    const float* wk    = (const float*)d_in[3];
    const float* bk    = (const float*)d_in[4];
    const float* wv    = (const float*)d_in[5];
    const float* bv    = (const float*)d_in[6];
    const float* wo    = (const float*)d_in[7];
    const float* bo    = (const float*)d_in[8];
    const float* ln1g  = (const float*)d_in[9];
    const float* ln1b  = (const float*)d_in[10];
    const float* ln2g  = (const float*)d_in[11];
    const float* ln2b  = (const float*)d_in[12];
    const float* pkmwq = (const float*)d_in[13];
    const float* bng   = (const float*)d_in[14];
    const float* bnb   = (const float*)d_in[15];
    const float* keys  = (const float*)d_in[16];
    const float* vals  = (const float*)d_in[17];
    float* out = (float*)d_out;

    float *ph, *pq, *pk, *pv, *patt, *pqf, *pqn, *pkeysT, *pdots;
    cudaGetSymbolAddress((void**)&ph,     g_h);
    cudaGetSymbolAddress((void**)&pq,     g_q);
    cudaGetSymbolAddress((void**)&pk,     g_k);
    cudaGetSymbolAddress((void**)&pv,     g_v);
    cudaGetSymbolAddress((void**)&patt,   g_att);
    cudaGetSymbolAddress((void**)&pqf,    g_qf);
    cudaGetSymbolAddress((void**)&pqn,    g_qn);
    cudaGetSymbolAddress((void**)&pkeysT, g_keysT);
    cudaGetSymbolAddress((void**)&pdots,  g_dots);

    // ---- attention block ----
    ln_kernel<<<NTOK, 256>>>(x, ln1g, ln1b);

    // QKV batched: z in {0,1,2}
    {
        GemmArgs a = {};
        a.A = ph; a.lda = DMODEL; a.ldw = DMODEL; a.ldc = DMODEL; a.K = DMODEL;
        a.resid = nullptr; a.ldr = 0;
        a.W[0] = wq; a.W[1] = wk; a.W[2] = wv;
        a.bias[0] = bq; a.bias[1] = bk; a.bias[2] = bv;
        a.C[0] = pq; a.C[1] = pk; a.C[2] = pv;
        gemm_kernel<<<dim3(DMODEL / 64, NTOK / 128, 3), 256>>>(a);
    }
    attn_kernel<<<dim3(2 * NHEAD, 8), 128>>>(pq, pk, pv, patt);
    // x1 = x + attn @ wo + bo  -> d_out
    {
        GemmArgs a = {};
        a.A = patt; a.lda = DMODEL; a.ldw = DMODEL; a.ldc = DMODEL; a.K = DMODEL;
        a.resid = x; a.ldr = DMODEL;
        a.W[0] = wo; a.bias[0] = bo; a.C[0] = out;
        gemm_kernel<<<dim3(DMODEL / 64, NTOK / 128, 1), 256>>>(a);
    }

    // ---- PKM block ----
    ln_kernel<<<NTOK, 256>>>(out, ln2g, ln2b);
    {
        GemmArgs a = {};
        a.A = ph; a.lda = DMODEL; a.ldw = DQF; a.ldc = DQF; a.K = DMODEL;
        a.W[0] = pkmwq; a.bias[0] = nullptr; a.C[0] = pqf;
        gemm_kernel<<<dim3(DQF / 64, NTOK / 128, 1), 256>>>(a);
    }
    bn_partial_kernel<<<dim3(4, 16), 256>>>();
    bn_finish_kernel<<<4, 256>>>();
    bn_apply_kernel<<<NTOK, 256>>>(bng, bnb);
    keysT_kernel<<<1024, 256>>>(keys);
    // dots: 8 batched GEMMs (z = 4p+h); A col offset 128*z, C col offset 256*z
    {
        GemmArgs a = {};
        a.A = pqn; a.lda = DQF; a.ldw = 256; a.ldc = 8 * 256; a.K = 128;
        for (int z = 0; z < 8; z++) {
            a.aOff[z] = 128 * z;
            a.W[z]    = pkeysT + (size_t)z * 128 * 256;
            a.bias[z] = nullptr;
            a.C[z]    = pdots + (size_t)z * 256;
        }
        gemm_kernel<<<dim3(256 / 64, NTOK / 128, 8), 256>>>(a);
    }
    topk_kernel<<<dim3(4, NTOK), 256>>>();
    gather_kernel<<<NTOK, 256>>>(vals, out);
}